// round 17
// baseline (speedup 1.0000x reference)
#include <cuda_runtime.h>
#include <math.h>
#include <stdint.h>

#define NB   2
#define L    2048
#define H    8
#define D    64
#define HD   512
#define LHD  1048576
#define P    16
#define C    64
#define NC   32
#define EPSF 1e-6f
#define SDT  68
#define EBS  32    // g_eb entry stride (floats) = one full 128B line per entry

// ---------------- scan-aggregate scratch + generation flags ----------------
__device__ float g_ks[P*NC*D], g_qs[P*NC*D];   // phase-1 chunk sums (sigmoid k/q)
__device__ float g_ko[P*NC*D], g_qi[P*NC*D];   // phase-2 chunk sums (k*so / q*si)
__device__ __align__(128) float g_eb[P*NC*EBS]; // es chunk sums, one cache line each
__device__ float g_kv[P*NC*D*D];               // KV chunk sums
__device__ unsigned g_f1[P*NC], g_f2[P*NC], g_f3[P*NC], g_f4[P*NC];
__device__ unsigned g_genc[P*NC];              // per-block persistent launch counter

typedef unsigned long long ull;
__device__ __forceinline__ ull pack2(float a, float b){
  ull r; asm("mov.b64 %0, {%1,%2};" : "=l"(r) : "f"(a), "f"(b)); return r;
}
__device__ __forceinline__ void fma2(ull &acc, ull a, ull b){
  asm("fma.rn.f32x2 %0, %1, %2, %0;" : "+l"(acc) : "l"(a), "l"(b));
}
__device__ __forceinline__ ull mul2(ull a, ull b){
  ull r; asm("mul.rn.f32x2 %0, %1, %2;" : "=l"(r) : "l"(a), "l"(b)); return r;
}
__device__ __forceinline__ float2 unpack2(ull v){
  float2 r; asm("mov.b64 {%0,%1}, %2;" : "=f"(r.x), "=f"(r.y) : "l"(v)); return r;
}
__device__ __forceinline__ float sigmoidf_(float x){ return 1.f/(1.f+__expf(-x)); }
__device__ __forceinline__ float f4get(const float4& v, int u){
  return (u==0)?v.x:(u==1)?v.y:(u==2)?v.z:v.w;
}
__device__ __forceinline__ float red4(float v){
  v += __shfl_xor_sync(0xffffffffu, v, 1);
  v += __shfl_xor_sync(0xffffffffu, v, 2);
  return v;
}
__device__ __forceinline__ unsigned ld_acq(const unsigned* p){
  unsigned v; asm volatile("ld.global.acquire.gpu.b32 %0, [%1];" : "=r"(v) : "l"(p)); return v;
}
__device__ __forceinline__ float ld_acq_f(const float* p){
  float v; asm volatile("ld.global.acquire.gpu.f32 %0, [%1];" : "=f"(v) : "l"(p)); return v;
}
__device__ __forceinline__ void st_rel(unsigned* p, unsigned v){
  asm volatile("st.global.release.gpu.b32 [%0], %1;" :: "l"(p), "r"(v) : "memory");
}
__device__ __forceinline__ void spin_gen(const unsigned* f, unsigned gen){
  int it = 0;
  while((int)(ld_acq(f) - gen) < 0){
    __nanosleep(it < 16 ? 32 : 64);
    it++;
  }
}

// ---------------- THE fused kernel (p = fast grid dim, gen flags) ----------------
__global__ void __launch_bounds__(256,3) k_fused(const float* __restrict__ Q,
                                                 const float* __restrict__ K,
                                                 const float* __restrict__ V,
                                                 float* __restrict__ OUT){
  extern __shared__ float sm[];
  float* sqs = sm;             // sigmoid(q) [l][d] stride 68; scaled in place later
  float* skT = sm + C*SDT;     // sigmoid(k)^T [d][j] stride 68; reused as vss [j][m] s64
  float* STs = sm + 2*C*SDT;   // S^T [j][l] stride 68  (STs[j*68+l] = S[l][j])
  float* skr = sm + 3*C*SDT;   // sigmoid(k) rows [j][d] s64; reused as kvs [d][m] s64
  float* vss = skT;
  float* kvs = skr;
  __shared__ float rsk[C], rsq[C], d1s[C], d2s[C], b3c[C], b4c[C], sis[C], sos[C];
  __shared__ float kpre[D], qpre[D], kpre2[D], qpre2[D], facs[C], essh[C], sa_s[C], comp[C];
  __shared__ float prefsh, wtot0;
  __shared__ unsigned gen_sh;

  int p = blockIdx.x, c = blockIdx.y, t = threadIdx.x;   // p FAST
  int pc = p*NC + c;
  const float* Qb = Q + (size_t)(p>>3)*LHD + (size_t)c*C*HD + (size_t)(p&7)*D;
  const float* Kb = K + (size_t)(p>>3)*LHD + (size_t)c*C*HD + (size_t)(p&7)*D;
  const float* Vb = V + (size_t)(p>>3)*LHD + (size_t)c*C*HD + (size_t)(p&7)*D;

  // generation for this launch (per-pc persistent counter; stream order makes this safe)
  if(t==0){ unsigned g = g_genc[pc] + 1u; g_genc[pc] = g; gen_sh = g; }

  // ---- load tiles, sigmoid ----
  #pragma unroll
  for(int k=0;k<4;k++){
    int i = t + k*256;
    int row = i>>4, col4 = (i&15)*4;
    float4 q4 = *(const float4*)(Qb + (size_t)row*HD + col4);
    q4.x=sigmoidf_(q4.x); q4.y=sigmoidf_(q4.y); q4.z=sigmoidf_(q4.z); q4.w=sigmoidf_(q4.w);
    *(float4*)(sqs + row*SDT + col4) = q4;
    float4 k4 = *(const float4*)(Kb + (size_t)row*HD + col4);
    k4.x=sigmoidf_(k4.x); k4.y=sigmoidf_(k4.y); k4.z=sigmoidf_(k4.z); k4.w=sigmoidf_(k4.w);
    *(float4*)(skr + row*D + col4) = k4;
    skT[(col4  )*SDT + row] = k4.x;
    skT[(col4+1)*SDT + row] = k4.y;
    skT[(col4+2)*SDT + row] = k4.z;
    skT[(col4+3)*SDT + row] = k4.w;
  }
  __syncthreads();
  unsigned gen = gen_sh;

  int ls = t>>2, gs = t&3;
  // ---- chunk sums, publish f1 EARLY ----
  { float a=0.f, b=0.f;
    #pragma unroll
    for(int u=0;u<16;u++){
      int j = 4*u + gs;
      a += skT[ls*SDT + j];
      b += sqs[j*SDT + ls];
    }
    a = red4(a); b = red4(b);
    if(gs==0){ g_ks[pc*D + ls] = a; g_qs[pc*D + ls] = b; }
  }
  __syncthreads();
  if(t==0) st_rel(&g_f1[pc], gen);

  // ---- row sums rsk/rsq (prefix-independent) ----
  { float rk=0.f, rq=0.f;
    #pragma unroll
    for(int u=0;u<16;u++){
      int d = 4*u + gs;
      rk += skT[d*SDT + ls];
    }
    #pragma unroll
    for(int u=0;u<4;u++){
      int dd = 16*gs + 4*u;
      float4 q4 = *(const float4*)(sqs + ls*SDT + dd);
      rq += q4.x+q4.y+q4.z+q4.w;
    }
    rk = red4(rk); rq = red4(rq);
    if(gs==0){ rsk[ls]=rk; rsq[ls]=rq; }
  }

  // ---- gram: 4l x 4j tiles -> STs (prefix-independent) ----
  int l0 = 4*(t>>4), j0 = 4*(t&15);
  { ull acc[8];
    #pragma unroll
    for(int m=0;m<8;m++) acc[m]=0ull;
    #pragma unroll 4
    for(int dq=0; dq<D; dq+=4){
      float4 q4[4];
      #pragma unroll
      for(int ll=0;ll<4;ll++) q4[ll] = *(const float4*)(sqs + (l0+ll)*SDT + dq);
      #pragma unroll
      for(int du=0;du<4;du++){
        double2 ka = *(const double2*)(skT + (dq+du)*SDT + j0);
        ull k0=(ull)__double_as_longlong(ka.x), k1=(ull)__double_as_longlong(ka.y);
        #pragma unroll
        for(int ll=0;ll<4;ll++){
          float qv = f4get(q4[ll], du);
          ull q2 = pack2(qv,qv);
          fma2(acc[ll*2],   q2, k0);
          fma2(acc[ll*2+1], q2, k1);
        }
      }
    }
    float vals[4][4];
    #pragma unroll
    for(int ll=0;ll<4;ll++){
      float2 a0=unpack2(acc[ll*2]), a1=unpack2(acc[ll*2+1]);
      vals[ll][0]=a0.x; vals[ll][1]=a0.y; vals[ll][2]=a1.x; vals[ll][3]=a1.y;
    }
    #pragma unroll
    for(int jj=0;jj<4;jj++)
      *(float4*)(STs + (j0+jj)*SDT + l0) =
        make_float4(vals[0][jj], vals[1][jj], vals[2][jj], vals[3][jj]);
  }
  __syncthreads();

  // ---- causal sums of S (prefix-independent) ----
  { float d1=0.f, d2=0.f;
    for(int i=gs; i<=ls; i+=4){
      d1 += STs[i*SDT + ls] + EPSF*rsk[i];   // S[ls][i]
      d2 += STs[ls*SDT + i] + EPSF*rsq[i];   // S[i][ls]
    }
    d1 = red4(d1); d2 = red4(d2);
    if(gs==0){ d1s[ls]=d1; d2s[ls]=d2; }
  }

  // ---- L1 wait (overlapped by gram+causal above) ----
  if(c > 0){
    if(t < c) spin_gen(&g_f1[p*NC + t], gen);
    __syncthreads();
    if(t < 64){ float a=0.f; for(int i=0;i<c;i++) a += __ldg(&g_ks[(p*NC+i)*D + t]); kpre[t]=a; }
    else if(t < 128){ int d=t-64; float a=0.f; for(int i=0;i<c;i++) a += __ldg(&g_qs[(p*NC+i)*D + d]); qpre[d]=a; }
  } else {
    if(t < 64) kpre[t]=0.f; else if(t < 128) qpre[t-64]=0.f;
  }
  __syncthreads();

  // ---- b1/b2 prefix dots -> si/so ----
  { float b1=0.f, b2=0.f;
    #pragma unroll
    for(int u=0;u<4;u++){
      int dd = 16*gs + 4*u;
      float4 q4 = *(const float4*)(sqs + ls*SDT + dd);
      b1 += (q4.x+EPSF)*(kpre[dd]+EPSF) + (q4.y+EPSF)*(kpre[dd+1]+EPSF)
          + (q4.z+EPSF)*(kpre[dd+2]+EPSF) + (q4.w+EPSF)*(kpre[dd+3]+EPSF);
    }
    #pragma unroll
    for(int u=0;u<16;u++){
      int d = 4*u + gs;
      float kv = skT[d*SDT + ls];
      b2 += (kv+EPSF)*(qpre[d]+EPSF);
    }
    b1 = red4(b1); b2 = red4(b2);
    if(gs==0){
      float nrm = (float)(c*C + ls + 1);
      sis[ls] = nrm/(b1 + d1s[ls]);
      sos[ls] = nrm/(b2 + d2s[ls]);
    }
  }
  __syncthreads();

  // ---- kso/qsi chunk sums, publish f2 ----
  { float a1=0.f, a2=0.f;
    #pragma unroll
    for(int u=0;u<16;u++){
      int j = 4*u + gs;
      a1 += skT[ls*SDT + j]*sos[j];
      a2 += sqs[j*SDT + ls]*sis[j];
    }
    a1 = red4(a1); a2 = red4(a2);
    if(gs==0){ g_ko[pc*D + ls] = a1; g_qi[pc*D + ls] = a2; }
  }
  __syncthreads();
  if(t==0) st_rel(&g_f2[pc], gen);

  // ---- conserved causal partials (prefix-independent; hides L2) ----
  { float b3=0.f, b4=0.f;
    for(int i=gs; i<=ls; i+=4){
      b3 += sos[i]*(STs[i*SDT + ls] + EPSF*rsk[i]);
      b4 += sis[i]*(STs[ls*SDT + i] + EPSF*rsq[i]);
    }
    b3 = red4(b3); b4 = red4(b4);
    if(gs==0){ b3c[ls]=b3; b4c[ls]=b4; }
  }

  // ---- L2 wait ----
  if(c > 0){
    if(t < c) spin_gen(&g_f2[p*NC + t], gen);
    __syncthreads();
    if(t < 64){ float a=0.f; for(int i=0;i<c;i++) a += __ldg(&g_ko[(p*NC+i)*D + t]); kpre2[t]=a; }
    else if(t < 128){ int d=t-64; float a=0.f; for(int i=0;i<c;i++) a += __ldg(&g_qi[(p*NC+i)*D + d]); qpre2[d]=a; }
  } else {
    if(t < 64) kpre2[t]=0.f; else if(t < 128) qpre2[t-64]=0.f;
  }
  __syncthreads();

  // ---- finish conserved: sa, es, q-scale factor ----
  { float b3=0.f, b4=0.f;
    #pragma unroll
    for(int u=0;u<4;u++){
      int dd = 16*gs + 4*u;
      float4 q4 = *(const float4*)(sqs + ls*SDT + dd);
      b3 += (q4.x+EPSF)*(kpre2[dd]+EPSF) + (q4.y+EPSF)*(kpre2[dd+1]+EPSF)
          + (q4.z+EPSF)*(kpre2[dd+2]+EPSF) + (q4.w+EPSF)*(kpre2[dd+3]+EPSF);
    }
    #pragma unroll
    for(int u=0;u<16;u++){
      int d = 4*u + gs;
      float kv = skT[d*SDT + ls];
      b4 += (kv+EPSF)*(qpre2[d]+EPSF);
    }
    b3 = red4(b3); b4 = red4(b4);
    if(gs==0){
      b3 += b3c[ls]; b4 += b4c[ls];
      float nrm = (float)(c*C + ls + 1);
      sa_s[ls] = sigmoidf_(b3/nrm);
      float cso = b4/nrm; cso = fminf(1.f, fmaxf(-1.f, cso));
      essh[ls] = __expf(cso);
      facs[ls] = sis[ls]/nrm;
    }
  }
  __syncthreads();

  // ---- scale sqs in place (q_scaled) ----
  #pragma unroll
  for(int k=0;k<4;k++){
    int i = t + k*256;
    int row = i>>4, col4 = (i&15)*4;
    float4 v = *(const float4*)(sqs + row*SDT + col4);
    float f = facs[row];
    *(float4*)(sqs + row*SDT + col4) = make_float4(v.x*f, v.y*f, v.z*f, v.w*f);
  }
  // ---- publish es chunk sum f3 ----
  if(t < 32){
    float v = essh[t] + essh[t+32];
    #pragma unroll
    for(int o=16;o;o>>=1) v += __shfl_down_sync(0xffffffffu, v, o);
    if(t==0){ g_eb[(size_t)pc*EBS] = v; st_rel(&g_f3[pc], gen); }
  }

  // ---- preload V into registers (hides global latency across L3 wait) ----
  float4 vreg[4];
  #pragma unroll
  for(int k=0;k<4;k++){
    int i = t + k*256;
    int row = i>>4, col4 = (i&15)*4;
    vreg[k] = *(const float4*)(Vb + (size_t)row*HD + col4);
  }

  // ---- L3 wait (merged spin+sum, warp 0; padded entries + acquire loads) ----
  if(t < 32){
    float s = 0.f;
    for(int i=t; i<c; i+=32){
      spin_gen(&g_f3[p*NC + i], gen);
      s += ld_acq_f(&g_eb[(size_t)(p*NC + i)*EBS]);
    }
    #pragma unroll
    for(int o=16;o;o>>=1) s += __shfl_down_sync(0xffffffffu, s, o);
    if(t==0) prefsh = s;
  }
  __syncthreads();
  // comp scan within chunk
  { float xscan = 0.f;
    if(t < 64){
      xscan = essh[t];
      #pragma unroll
      for(int o=1;o<32;o<<=1){
        float y = __shfl_up_sync(0xffffffffu, xscan, o);
        if((t&31) >= o) xscan += y;
      }
      if(t==31) wtot0 = xscan;
    }
    __syncthreads();
    if(t < 64){
      float cum = prefsh + xscan + ((t>=32)? wtot0 : 0.f);
      comp[t] = essh[t]/cum * (float)(c*C + t + 1);
    }
  }
  __syncthreads();

  // ---- vss = V*comp (overwrites skT; all skT uses done) ----
  #pragma unroll
  for(int k=0;k<4;k++){
    int i = t + k*256;
    int row = i>>4, col4 = (i&15)*4;
    float f = comp[row];
    *(float4*)(vss + row*D + col4) = make_float4(vreg[k].x*f, vreg[k].y*f, vreg[k].z*f, vreg[k].w*f);
  }
  __syncthreads();

  // ---- vkv: chunk KV aggregate, publish f4 ----
  int d0 = 4*(t>>4), m0 = 4*(t&15);
  { ull acc[8];
    #pragma unroll
    for(int m=0;m<8;m++) acc[m]=0ull;
    #pragma unroll 8
    for(int j=0;j<C;j++){
      float4 sk4 = *(const float4*)(skr + j*D + d0);
      double2 va = *(const double2*)(vss + j*D + m0);
      ull v0=(ull)__double_as_longlong(va.x), v1=(ull)__double_as_longlong(va.y);
      #pragma unroll
      for(int dd=0;dd<4;dd++){
        float a = f4get(sk4, dd);
        ull a2 = pack2(a,a);
        fma2(acc[dd*2],   a2, v0);
        fma2(acc[dd*2+1], a2, v1);
      }
    }
    float* gkv = g_kv + (size_t)pc*D*D;
    #pragma unroll
    for(int dd=0;dd<4;dd++){
      float2 u0=unpack2(acc[dd*2]), u1=unpack2(acc[dd*2+1]);
      *(float4*)(gkv + (d0+dd)*D + m0) = make_float4(u0.x,u0.y,u1.x,u1.y);
    }
  }
  __syncthreads();
  if(t==0) st_rel(&g_f4[pc], gen);

  // ---- out-intra BEFORE the L4 wait (prefix-independent) ----
  ull acc[8];
  #pragma unroll
  for(int m=0;m<8;m++) acc[m]=0ull;
  { int nf = l0 >> 2;
    for(int ib=0; ib<nf; ib++){
      float4 st4[4]; double2 va[4];
      #pragma unroll
      for(int u=0;u<4;u++){
        int i = 4*ib+u;
        st4[u] = *(const float4*)(STs + i*SDT + l0);
        va[u]  = *(const double2*)(vss + i*D + m0);
      }
      #pragma unroll
      for(int u=0;u<4;u++){
        ull v0=(ull)__double_as_longlong(va[u].x), v1=(ull)__double_as_longlong(va[u].y);
        #pragma unroll
        for(int ll=0;ll<4;ll++){
          float s = f4get(st4[u], ll);
          ull s2 = pack2(s,s);
          fma2(acc[ll*2],   s2, v0);
          fma2(acc[ll*2+1], s2, v1);
        }
      }
    }
    { float4 st4[4]; double2 va[4];
      #pragma unroll
      for(int u=0;u<4;u++){
        int i = l0+u;
        st4[u] = *(const float4*)(STs + i*SDT + l0);
        va[u]  = *(const double2*)(vss + i*D + m0);
      }
      #pragma unroll
      for(int u=0;u<4;u++){
        ull v0=(ull)__double_as_longlong(va[u].x), v1=(ull)__double_as_longlong(va[u].y);
        #pragma unroll
        for(int ll=0;ll<4;ll++){
          float s = (u <= ll) ? f4get(st4[u], ll) : 0.f;
          ull s2 = pack2(s,s);
          fma2(acc[ll*2],   s2, v0);
          fma2(acc[ll*2+1], s2, v1);
        }
      }
    }
    #pragma unroll
    for(int ll=0;ll<4;ll++){
      float f = facs[l0+ll];
      ull f2 = pack2(f,f);
      acc[ll*2]   = mul2(acc[ll*2],   f2);
      acc[ll*2+1] = mul2(acc[ll*2+1], f2);
    }
  }

  // ---- L4: merged spin+accumulate KV prefix (ascending order = deterministic) ----
  {
    float4 a0=make_float4(0,0,0,0), a1=a0, a2=a0, a3=a0;
    for(int i=0;i<c;i++){
      spin_gen(&g_f4[p*NC + i], gen);
      const float4* gkv = (const float4*)(g_kv + (size_t)(p*NC+i)*D*D);
      float4 w0 = __ldg(gkv + ((d0+0)*D + m0)/4);
      float4 w1 = __ldg(gkv + ((d0+1)*D + m0)/4);
      float4 w2 = __ldg(gkv + ((d0+2)*D + m0)/4);
      float4 w3 = __ldg(gkv + ((d0+3)*D + m0)/4);
      a0.x+=w0.x; a0.y+=w0.y; a0.z+=w0.z; a0.w+=w0.w;
      a1.x+=w1.x; a1.y+=w1.y; a1.z+=w1.z; a1.w+=w1.w;
      a2.x+=w2.x; a2.y+=w2.y; a2.z+=w2.z; a2.w+=w2.w;
      a3.x+=w3.x; a3.y+=w3.y; a3.z+=w3.z; a3.w+=w3.w;
    }
    // skr reads (vkv phase) ended before the pre-f4 __syncthreads; safe to overwrite
    *(float4*)(kvs + (d0+0)*D + m0) = a0;
    *(float4*)(kvs + (d0+1)*D + m0) = a1;
    *(float4*)(kvs + (d0+2)*D + m0) = a2;
    *(float4*)(kvs + (d0+3)*D + m0) = a3;
  }
  __syncthreads();

  // ---- out-inter: q_scaled @ KVprefix, then store ----
  {
    #pragma unroll 4
    for(int dq=0; dq<D; dq+=4){
      float4 q4[4];
      #pragma unroll
      for(int ll=0;ll<4;ll++) q4[ll] = *(const float4*)(sqs + (l0+ll)*SDT + dq);
      #pragma unroll
      for(int du=0;du<4;du++){
        double2 ka = *(const double2*)(kvs + (dq+du)*D + m0);
        ull k0=(ull)__double_as_longlong(ka.x), k1=(ull)__double_as_longlong(ka.y);
        #pragma unroll
        for(int ll=0;ll<4;ll++){
          float qv = f4get(q4[ll], du);
          ull q2 = pack2(qv,qv);
          fma2(acc[ll*2],   q2, k0);
          fma2(acc[ll*2+1], q2, k1);
        }
      }
    }
    float* op = OUT + (size_t)(p>>3)*LHD + (size_t)c*C*HD + (size_t)(p&7)*D;
    #pragma unroll
    for(int ll=0;ll<4;ll++){
      float sa = sa_s[l0+ll];
      float2 a0=unpack2(acc[ll*2]), a1=unpack2(acc[ll*2+1]);
      *(float4*)(op + (size_t)(l0+ll)*HD + m0) =
        make_float4(a0.x*sa, a0.y*sa, a1.x*sa, a1.y*sa);
    }
  }
}

// ---------------- launch ----------------
extern "C" void kernel_launch(void* const* d_in, const int* in_sizes, int n_in,
                              void* d_out, int out_size){
  const float* Q = (const float*)d_in[0];
  const float* K = (const float*)d_in[1];
  const float* V = (const float*)d_in[2];
  float* OUT = (float*)d_out;

  const int SM_FUSED = (3*C*SDT + C*D)*sizeof(float);   // 68608
  cudaFuncSetAttribute(k_fused, cudaFuncAttributeMaxDynamicSharedMemorySize, SM_FUSED);

  k_fused<<<dim3(P, NC), 256, SM_FUSED>>>(Q, K, V, OUT);
}